// round 6
// baseline (speedup 1.0000x reference)
#include <cuda_runtime.h>
#include <cstdint>

#define BB   16
#define LL   512
#define CC   256
#define MEL  4096

// ---------------------------------------------------------------------------
// Scratch (__device__ globals — allocations are forbidden)
// ---------------------------------------------------------------------------
__device__ float g_h1[BB * LL * CC];          // LN1 out (tf32-rounded) -> conv2 A
__device__ int   g_idx[BB * MEL];             // per-frame token index (-1 invalid)
__device__ float g_wcvt[2 * 3 * CC * CC];     // RNA-rounded weights, both convs

// ---------------------------------------------------------------------------
// helpers (arch-generic PTX)
// ---------------------------------------------------------------------------
__device__ __forceinline__ uint32_t f2tf(float f) {
    uint32_t u;
    asm("cvt.rna.tf32.f32 %0, %1;" : "=r"(u) : "f"(f));
    return u;
}
__device__ __forceinline__ float f2tff(float f) { return __uint_as_float(f2tf(f)); }

__device__ __forceinline__ void mma_tf32(float* d, const uint32_t* a, const uint32_t* b) {
    asm volatile(
        "mma.sync.aligned.m16n8k8.row.col.f32.tf32.tf32.f32 "
        "{%0,%1,%2,%3}, {%4,%5,%6,%7}, {%8,%9}, {%0,%1,%2,%3};"
        : "+f"(d[0]), "+f"(d[1]), "+f"(d[2]), "+f"(d[3])
        : "r"(a[0]), "r"(a[1]), "r"(a[2]), "r"(a[3]), "r"(b[0]), "r"(b[1]));
}

__device__ __forceinline__ uint32_t smem_u32(const void* p) {
    uint32_t a;
    asm("{ .reg .u64 t; cvta.to.shared.u64 t, %1; cvt.u32.u64 %0, t; }"
        : "=r"(a) : "l"(p));
    return a;
}
#define CP_ASYNC16(dst, src) \
    asm volatile("cp.async.ca.shared.global [%0], [%1], 16;" :: "r"(dst), "l"(src))
#define CP_COMMIT() asm volatile("cp.async.commit_group;" ::: "memory")
#define CP_WAIT1()  asm volatile("cp.async.wait_group 1;" ::: "memory")
#define CP_WAIT0()  asm volatile("cp.async.wait_group 0;" ::: "memory")

// smem geometry (floats). Strides ≡ 8 (mod 32) -> conflict-free frag loads.
#define SA_STR 264
#define SB_STR 264
#define SA_FLOATS (66 * SA_STR)          // 17424
#define SB_FLOATS (64 * SB_STR)          // 16896
#define SMEM_FLOATS (SA_FLOATS + 2 * SB_FLOATS)
#define SMEM_BYTES  (SMEM_FLOATS * 4)    // 204864

// ---------------------------------------------------------------------------
// Prep: weight RNA pre-round (blocks 0..191) + cumsum/frame-idx (blocks 192..207)
// ---------------------------------------------------------------------------
__global__ void __launch_bounds__(512) prep_kernel(const float* __restrict__ w1,
                                                   const float* __restrict__ w2,
                                                   const int* __restrict__ dur)
{
    if (blockIdx.x < 192) {
        const int n = 3 * CC * CC;
        int i = blockIdx.x * 512 + threadIdx.x;
        g_wcvt[i]             = f2tff(w1[i]);
        g_wcvt[i + 98304]     = f2tff(w1[i + 98304]);
        g_wcvt[n + i]         = f2tff(w2[i]);
        g_wcvt[n + i + 98304] = f2tff(w2[i + 98304]);
        return;
    }
    __shared__ int s[LL];
    int b = blockIdx.x - 192, tid = threadIdx.x;
    s[tid] = dur[b * LL + tid];
    __syncthreads();
    for (int off = 1; off < LL; off <<= 1) {
        int v = (tid >= off) ? s[tid - off] : 0;
        __syncthreads();
        s[tid] += v;
        __syncthreads();
    }
    int total = s[LL - 1];
#pragma unroll
    for (int r = 0; r < 8; r++) {
        int t = tid + r * 512;
        int lo = 0, hi = LL;
        while (lo < hi) {
            int mid = (lo + hi) >> 1;
            if (s[mid] <= t) lo = mid + 1; else hi = mid;
        }
        g_idx[b * MEL + t] = (t < total) ? min(lo, LL - 1) : -1;
    }
}

// ---------------------------------------------------------------------------
// Fused conv1d(K=3,SAME)+bias+ReLU+LN [+linear head if FINAL]
// CTA = [64 l x 256 f], 512 threads / 16 warps, warp tile 32x32.
// A resident in smem; B cp.async double-buffered. Conv1 streams regulate out.
// ---------------------------------------------------------------------------
template <bool FINAL>
__global__ void __launch_bounds__(512, 1)
conv_mma_kernel(const float* __restrict__ xin,
                const float* __restrict__ bias,
                const float* __restrict__ gamma,
                const float* __restrict__ beta,
                const float* __restrict__ linw,
                const float* __restrict__ linb,
                float* __restrict__ predout,
                float* __restrict__ regout)
{
    extern __shared__ __align__(16) float smem[];
    float* sA = smem;
    float* sB[2] = { smem + SA_FLOATS, smem + SA_FLOATS + SB_FLOATS };
    const uint32_t sb_u32[2] = { smem_u32(sB[0]), smem_u32(sB[1]) };

    const int tid  = threadIdx.x;
    const int warp = tid >> 5, lane = tid & 31;
    const int g = lane >> 2, q = lane & 3;
    const int mh = warp & 1;                       // m-half: rows mh*32..mh*32+31
    const int nw = warp >> 1;                      // n-warp: cols nw*32..nw*32+31
    const int n0 = nw * 32;
    const int m0 = mh * 32;
    const int b  = blockIdx.y;
    const int l0 = blockIdx.x * 64;
    const int CONV = FINAL ? 1 : 0;
    const float* inb = (FINAL ? (const float*)g_h1 : xin) + (size_t)b * LL * CC;
    const float* wbase = g_wcvt + (size_t)CONV * 3 * CC * CC;

    auto stageB = [&](int it, int buf) {
        const int k = it >> 2, c0 = (it & 3) * 64;
        const float* src = wbase + ((size_t)(k * CC + c0)) * CC;
#pragma unroll
        for (int i = 0; i < 8; i++) {
            int idx = tid + i * 512;               // 0..4095
            int c = idx >> 6, f4 = idx & 63;
            CP_ASYNC16(sb_u32[buf] + (uint32_t)(c * SB_STR + f4 * 4) * 4,
                       src + (size_t)c * CC + f4 * 4);
        }
        CP_COMMIT();
    };
    stageB(0, 0);
    stageB(1, 1);

#pragma unroll 3
    for (int i = 0; i < 9; i++) {
        int idx = tid + i * 512;                   // need 4224
        if (idx < 66 * 64) {
            int sr = idx >> 6, f4 = idx & 63;
            int grow = l0 + sr - 1;
            float4 v = make_float4(0.f, 0.f, 0.f, 0.f);
            if (grow >= 0 && grow < LL)
                v = *(const float4*)(inb + (size_t)grow * CC + f4 * 4);
            if (!FINAL) { v.x = f2tff(v.x); v.y = f2tff(v.y);
                          v.z = f2tff(v.z); v.w = f2tff(v.w); }
            *(float4*)(sA + sr * SA_STR + f4 * 4) = v;
        }
    }

    float acc[2][4][4];                            // [mt][nt][creg]
#pragma unroll
    for (int mt = 0; mt < 2; mt++)
#pragma unroll
        for (int nt = 0; nt < 4; nt++)
#pragma unroll
            for (int r = 0; r < 4; r++) acc[mt][nt][r] = 0.f;

    for (int it = 0; it < 12; it++) {
        const int ktap = it >> 2, c0 = (it & 3) * 64;
        const int buf = it & 1;
        if (it < 11) CP_WAIT1(); else CP_WAIT0();
        __syncthreads();

        const float* bp = sB[buf];
        const float* ap = sA + (ktap + m0 + g) * SA_STR + c0 + q;
#pragma unroll
        for (int ks = 0; ks < 8; ks++) {
            uint32_t af[2][4], bf[4][2];
#pragma unroll
            for (int mt = 0; mt < 2; mt++) {
                const float* a0 = ap + mt * (16 * SA_STR) + ks * 8;
                af[mt][0] = __float_as_uint(a0[0]);
                af[mt][1] = __float_as_uint(a0[8 * SA_STR]);
                af[mt][2] = __float_as_uint(a0[4]);
                af[mt][3] = __float_as_uint(a0[8 * SA_STR + 4]);
            }
#pragma unroll
            for (int nt = 0; nt < 4; nt++) {
                bf[nt][0] = __float_as_uint(bp[(ks * 8 + q) * SB_STR + n0 + nt * 8 + g]);
                bf[nt][1] = __float_as_uint(bp[(ks * 8 + q + 4) * SB_STR + n0 + nt * 8 + g]);
            }
#pragma unroll
            for (int mt = 0; mt < 2; mt++)
#pragma unroll
                for (int nt = 0; nt < 4; nt++)
                    mma_tf32(acc[mt][nt], af[mt], bf[nt]);
        }
        __syncthreads();
        if (it + 2 < 12) stageB(it + 2, buf);

        // ---- interleaved length regulation (conv1 only) ----
        if (!FINAL) {
            int ix[6];
            float4 vv[6];
#pragma unroll
            for (int u = 0; u < 6; u++) {
                int s = it * 6 + u;
                ix[u] = -1;
                if (s < 64)
                    ix[u] = g_idx[b * MEL + blockIdx.x * 512 + ((tid + s * 512) >> 6)];
            }
#pragma unroll
            for (int u = 0; u < 6; u++) {
                vv[u] = make_float4(0.f, 0.f, 0.f, 0.f);
                if (ix[u] >= 0) {
                    int s = it * 6 + u;
                    int c4 = (tid + s * 512) & 63;
                    vv[u] = *(const float4*)(xin + ((size_t)b * LL + ix[u]) * CC + c4 * 4);
                }
            }
#pragma unroll
            for (int u = 0; u < 6; u++) {
                int s = it * 6 + u;
                if (s < 64) {
                    int j = tid + s * 512;
                    int fr = j >> 6, c4 = j & 63;
                    *(float4*)(regout + ((size_t)b * MEL + blockIdx.x * 512 + fr) * CC + c4 * 4) = vv[u];
                }
            }
        }
    }
    __syncthreads();

    // ---- epilogue: bias + ReLU + LN (fused), optional linear head ----
    float bi[8], ga[8], be[8], lw[8];
#pragma unroll
    for (int nt = 0; nt < 4; nt++)
#pragma unroll
        for (int j = 0; j < 2; j++) {
            int c = n0 + nt * 8 + 2 * q + j;
            bi[nt * 2 + j] = __ldg(bias + c);
            ga[nt * 2 + j] = __ldg(gamma + c);
            be[nt * 2 + j] = __ldg(beta + c);
            if (FINAL) lw[nt * 2 + j] = __ldg(linw + c);
        }

    float v[2][2][8];
    float2* red   = (float2*)sA;                   // [64 rows][8 n-warps]
    float2* stats = (float2*)sA + 512;             // [64]

#pragma unroll
    for (int mt = 0; mt < 2; mt++)
#pragma unroll
        for (int h = 0; h < 2; h++) {
            float s = 0.f, s2 = 0.f;
#pragma unroll
            for (int nt = 0; nt < 4; nt++)
#pragma unroll
                for (int j = 0; j < 2; j++) {
                    float x = acc[mt][nt][h * 2 + j] + bi[nt * 2 + j];
                    x = fmaxf(x, 0.f);
                    v[mt][h][nt * 2 + j] = x;
                    s += x; s2 += x * x;
                }
            s  += __shfl_xor_sync(0xffffffffu, s, 1);
            s2 += __shfl_xor_sync(0xffffffffu, s2, 1);
            s  += __shfl_xor_sync(0xffffffffu, s, 2);
            s2 += __shfl_xor_sync(0xffffffffu, s2, 2);
            if (q == 0)
                red[(m0 + mt * 16 + g + 8 * h) * 8 + nw] = make_float2(s, s2);
        }
    __syncthreads();
    if (tid < 64) {
        float s = 0.f, s2 = 0.f;
#pragma unroll
        for (int wv = 0; wv < 8; wv++) {
            float2 p = red[tid * 8 + wv];
            s += p.x; s2 += p.y;
        }
        float mu = s * (1.f / 256.f);
        float var = s2 * (1.f / 256.f) - mu * mu;
        stats[tid] = make_float2(mu, rsqrtf(var + 1e-5f));
    }
    __syncthreads();

    if (!FINAL) {
#pragma unroll
        for (int mt = 0; mt < 2; mt++)
#pragma unroll
            for (int h = 0; h < 2; h++) {
                int r = m0 + mt * 16 + g + 8 * h;
                float2 st = stats[r];
                float* orow = g_h1 + ((size_t)b * LL + l0 + r) * CC;
#pragma unroll
                for (int nt = 0; nt < 4; nt++) {
                    float2 o;
                    o.x = f2tff((v[mt][h][nt * 2]     - st.x) * st.y * ga[nt * 2]     + be[nt * 2]);
                    o.y = f2tff((v[mt][h][nt * 2 + 1] - st.x) * st.y * ga[nt * 2 + 1] + be[nt * 2 + 1]);
                    *(float2*)(orow + n0 + nt * 8 + 2 * q) = o;
                }
            }
    } else {
        float* dred = sA + 2048;                   // [64 rows][8 n-warps]
#pragma unroll
        for (int mt = 0; mt < 2; mt++)
#pragma unroll
            for (int h = 0; h < 2; h++) {
                int r = m0 + mt * 16 + g + 8 * h;
                float2 st = stats[r];
                float d = 0.f;
#pragma unroll
                for (int p = 0; p < 8; p++)
                    d += ((v[mt][h][p] - st.x) * st.y * ga[p] + be[p]) * lw[p];
                d += __shfl_xor_sync(0xffffffffu, d, 1);
                d += __shfl_xor_sync(0xffffffffu, d, 2);
                if (q == 0) dred[r * 8 + nw] = d;
            }
        __syncthreads();
        if (tid < 64) {
            float d = 0.f;
#pragma unroll
            for (int wv = 0; wv < 8; wv++) d += dred[tid * 8 + wv];
            predout[b * LL + l0 + tid] = d + __ldg(linb);
        }
    }
}

// ---------------------------------------------------------------------------
extern "C" void kernel_launch(void* const* d_in, const int* in_sizes, int n_in,
                              void* d_out, int out_size)
{
    const float* x    = (const float*)d_in[0];
    const int*   dur  = (const int*)d_in[1];
    const float* c1w  = (const float*)d_in[2];
    const float* c1b  = (const float*)d_in[3];
    const float* ln1g = (const float*)d_in[4];
    const float* ln1b = (const float*)d_in[5];
    const float* c2w  = (const float*)d_in[6];
    const float* c2b  = (const float*)d_in[7];
    const float* ln2g = (const float*)d_in[8];
    const float* ln2b = (const float*)d_in[9];
    const float* linw = (const float*)d_in[10];
    const float* linb = (const float*)d_in[11];

    float* out  = (float*)d_out;
    float* pred = out + (size_t)BB * MEL * CC;

    cudaFuncSetAttribute(conv_mma_kernel<false>,
                         cudaFuncAttributeMaxDynamicSharedMemorySize, SMEM_BYTES);
    cudaFuncSetAttribute(conv_mma_kernel<true>,
                         cudaFuncAttributeMaxDynamicSharedMemorySize, SMEM_BYTES);

    prep_kernel<<<192 + BB, 512>>>(c1w, c2w, dur);

    dim3 cgrid(LL / 64, BB);
    conv_mma_kernel<false><<<cgrid, 512, SMEM_BYTES>>>(x, c1b, ln1g, ln1b,
                                                       nullptr, nullptr, nullptr, out);
    conv_mma_kernel<true><<<cgrid, 512, SMEM_BYTES>>>(x, c2b, ln2g, ln2b,
                                                      linw, linb, pred, nullptr);
}